// round 1
// baseline (speedup 1.0000x reference)
#include <cuda_runtime.h>
#include <math.h>

#define BATCH 32
#define TLEN  1024
#define IDIM  512
#define HDIM  1024
#define G4    4096   // 4*H

// ---------------- scratch (static device arrays: allocation-free) ----------
__device__ float g_Xg[(size_t)BATCH * TLEN * G4];   // 512 MB: [t*32+b][4096]
__device__ float g_h[2][HDIM * BATCH];              // double buffer, [k][b] layout
__device__ volatile unsigned g_bar;                 // grid barrier counter (monotonic per launch)
__device__ unsigned g_done;                         // end-of-kernel reset counter

// ======================= Kernel 1: Xg = X @ W_ih^T + b_ih + b_hh ===========
// X: [32768, 512] row-major (rows n = b*1024 + t), W_ih: [4096, 512] row-major.
// Output layout: g_Xg[(t*32 + b)*4096 + col].
#define BM 128
#define BN 64
#define BK 16

__global__ __launch_bounds__(256) void xg_gemm(const float* __restrict__ X,
                                               const float* __restrict__ Wih,
                                               const float* __restrict__ bih,
                                               const float* __restrict__ bhh) {
    __shared__ float sA[BM][BK + 1];
    __shared__ float sB[BN][BK + 1];

    const int tid = threadIdx.x;
    const int tx = tid & 15;        // 16 col-groups of 4
    const int ty = tid >> 4;        // 16 row-groups of 8
    const int n0 = blockIdx.y * BM;
    const int c0 = blockIdx.x * BN;

    float acc[8][4];
#pragma unroll
    for (int i = 0; i < 8; ++i)
#pragma unroll
        for (int j = 0; j < 4; ++j) acc[i][j] = 0.f;

    for (int k0 = 0; k0 < IDIM; k0 += BK) {
        // Load A tile: 128x16 floats, 8 per thread
        {
            const int m = tid >> 1;
            const int kk = (tid & 1) * 8;
            const float* src = X + (size_t)(n0 + m) * IDIM + k0 + kk;
            float4 v0 = *(const float4*)(src);
            float4 v1 = *(const float4*)(src + 4);
            sA[m][kk + 0] = v0.x; sA[m][kk + 1] = v0.y;
            sA[m][kk + 2] = v0.z; sA[m][kk + 3] = v0.w;
            sA[m][kk + 4] = v1.x; sA[m][kk + 5] = v1.y;
            sA[m][kk + 6] = v1.z; sA[m][kk + 7] = v1.w;
        }
        // Load B tile: 64x16 floats, 4 per thread
        {
            const int m = tid >> 2;
            const int kk = (tid & 3) * 4;
            float4 v = *(const float4*)(Wih + (size_t)(c0 + m) * IDIM + k0 + kk);
            sB[m][kk + 0] = v.x; sB[m][kk + 1] = v.y;
            sB[m][kk + 2] = v.z; sB[m][kk + 3] = v.w;
        }
        __syncthreads();

#pragma unroll
        for (int kk = 0; kk < BK; ++kk) {
            float af[8], bf[4];
#pragma unroll
            for (int i = 0; i < 8; ++i) af[i] = sA[ty * 8 + i][kk];
#pragma unroll
            for (int j = 0; j < 4; ++j) bf[j] = sB[tx * 4 + j][kk];
#pragma unroll
            for (int i = 0; i < 8; ++i)
#pragma unroll
                for (int j = 0; j < 4; ++j)
                    acc[i][j] = fmaf(af[i], bf[j], acc[i][j]);
        }
        __syncthreads();
    }

    // Epilogue: add biases, scatter to [t][b] layout
    const int col = c0 + tx * 4;
    float4 bi = *(const float4*)(bih + col);
    float4 bh = *(const float4*)(bhh + col);
    float4 bias;
    bias.x = bi.x + bh.x; bias.y = bi.y + bh.y;
    bias.z = bi.z + bh.z; bias.w = bi.w + bh.w;

#pragma unroll
    for (int i = 0; i < 8; ++i) {
        const int n = n0 + ty * 8 + i;
        const int b = n >> 10;        // n / 1024
        const int t = n & 1023;
        float4 o;
        o.x = acc[i][0] + bias.x;
        o.y = acc[i][1] + bias.y;
        o.z = acc[i][2] + bias.z;
        o.w = acc[i][3] + bias.w;
        *(float4*)&g_Xg[((size_t)(t * BATCH + b)) * G4 + col] = o;
    }
}

// ======================= Kernel 2: persistent recurrence ===================
// 128 blocks x 256 threads. Block blk owns hidden units [blk*8, blk*8+8),
// i.e. 32 gate rows (local row lr = gate*8 + uu  <->  global row gate*H + blk*8 + uu).
// W_hh slice (32x1024 fp32 = 128KB) resides in SMEM for the entire kernel.
#define GRID 128
#define NTH  256
#define KCH  256   // h K-chunk staged in SMEM

__global__ __launch_bounds__(NTH, 1) void lstm_rec(const float* __restrict__ Whh,
                                                   float* __restrict__ out) {
    extern __shared__ float smem[];
    float* sW = smem;                  // 32*1024 floats
    float* sH = smem + 32 * HDIM;      // KCH*32 floats
    __shared__ float sG[32 * 32];      // gate pre-activations [lr][b]
    __shared__ float sC[NTH];          // cell state [uu][b]

    const int tid = threadIdx.x;
    const int blk = blockIdx.x;
    const int lane = tid & 31;
    const int warp = tid >> 5;         // 8 warps, warp w -> rows 4w..4w+3
    const int uu = tid >> 5;           // epilogue: unit-local
    const int bb = tid & 31;           // epilogue: batch
    const int gu = blk * 8 + uu;       // global hidden unit

    // Load W_hh slice into SMEM (once)
    for (int i = tid; i < 32 * (HDIM / 4); i += NTH) {
        const int lr = i >> 8;               // 256 float4 per row
        const int kq = i & 255;
        const int g = lr >> 3;
        const int u = lr & 7;
        const int grow = g * HDIM + blk * 8 + u;
        ((float4*)sW)[i] = __ldg((const float4*)(Whh + (size_t)grow * HDIM) + kq);
    }
    sC[tid] = 0.f;
    // Zero own slice of h buffer 0 (fresh each launch/replay)
    g_h[0][gu * BATCH + bb] = 0.f;

    const float4* w0 = (const float4*)(sW + (warp * 4 + 0) * HDIM);
    const float4* w1 = (const float4*)(sW + (warp * 4 + 1) * HDIM);
    const float4* w2 = (const float4*)(sW + (warp * 4 + 2) * HDIM);
    const float4* w3 = (const float4*)(sW + (warp * 4 + 3) * HDIM);

    for (int t = 0; t < TLEN; ++t) {
        // ---- grid barrier: makes previous step's h (and init) visible ----
        __syncthreads();
        if (tid == 0) {
            __threadfence();
            atomicAdd((unsigned*)&g_bar, 1u);
            const unsigned target = (unsigned)(t + 1) * GRID;
            while (g_bar < target) { }
        }
        __syncthreads();

        // Prefetch this thread's Xg gate inputs (consumed after the GEMM)
        const size_t xbase = ((size_t)(t * BATCH + bb)) * G4 + gu;
        const float xi = __ldg(&g_Xg[xbase]);
        const float xf = __ldg(&g_Xg[xbase + HDIM]);
        const float xg = __ldg(&g_Xg[xbase + 2 * HDIM]);
        const float xo = __ldg(&g_Xg[xbase + 3 * HDIM]);

        const float* hcur = g_h[t & 1];
        float acc0 = 0.f, acc1 = 0.f, acc2 = 0.f, acc3 = 0.f;

        for (int kc = 0; kc < HDIM / KCH; ++kc) {
            // Stage h chunk [KCH][32] into SMEM, L2-coherent (bypass L1: other
            // SMs wrote this buffer; L1 is only flushed at launch boundaries).
            const float4* src = (const float4*)(hcur + kc * (KCH * BATCH));
            for (int i = tid; i < KCH * BATCH / 4; i += NTH)
                ((float4*)sH)[i] = __ldcg(&src[i]);
            __syncthreads();

            const int kb = kc * (KCH / 4);
#pragma unroll 4
            for (int kk = 0; kk < KCH; kk += 4) {
                const float h0 = sH[(kk + 0) * 32 + lane];
                const float h1 = sH[(kk + 1) * 32 + lane];
                const float h2 = sH[(kk + 2) * 32 + lane];
                const float h3 = sH[(kk + 3) * 32 + lane];
                const float4 a = w0[kb + (kk >> 2)];
                const float4 b = w1[kb + (kk >> 2)];
                const float4 c = w2[kb + (kk >> 2)];
                const float4 d = w3[kb + (kk >> 2)];
                acc0 = fmaf(a.x, h0, acc0); acc0 = fmaf(a.y, h1, acc0);
                acc0 = fmaf(a.z, h2, acc0); acc0 = fmaf(a.w, h3, acc0);
                acc1 = fmaf(b.x, h0, acc1); acc1 = fmaf(b.y, h1, acc1);
                acc1 = fmaf(b.z, h2, acc1); acc1 = fmaf(b.w, h3, acc1);
                acc2 = fmaf(c.x, h0, acc2); acc2 = fmaf(c.y, h1, acc2);
                acc2 = fmaf(c.z, h2, acc2); acc2 = fmaf(c.w, h3, acc2);
                acc3 = fmaf(d.x, h0, acc3); acc3 = fmaf(d.y, h1, acc3);
                acc3 = fmaf(d.z, h2, acc3); acc3 = fmaf(d.w, h3, acc3);
            }
            __syncthreads();
        }

        // Publish gate pre-activations to SMEM, then cell update per (uu, bb)
        sG[(warp * 4 + 0) * 32 + lane] = acc0;
        sG[(warp * 4 + 1) * 32 + lane] = acc1;
        sG[(warp * 4 + 2) * 32 + lane] = acc2;
        sG[(warp * 4 + 3) * 32 + lane] = acc3;
        __syncthreads();

        const float pi = sG[(0 * 8 + uu) * 32 + bb] + xi;
        const float pf = sG[(1 * 8 + uu) * 32 + bb] + xf;
        const float pg = sG[(2 * 8 + uu) * 32 + bb] + xg;
        const float po = sG[(3 * 8 + uu) * 32 + bb] + xo;

        const float ig = 1.f / (1.f + expf(-pi));
        const float fg = 1.f / (1.f + expf(-pf));
        const float gg = tanhf(pg);
        const float og = 1.f / (1.f + expf(-po));

        const float cold = sC[tid];
        const float cnew = fmaf(fg, cold, ig * gg);
        sC[tid] = cnew;
        const float hnew = og * tanhf(cnew);

        g_h[(t + 1) & 1][gu * BATCH + bb] = hnew;
        out[(size_t)bb * TLEN * HDIM + (size_t)t * HDIM + gu] = hnew;
        if (t == TLEN - 1) {
            out[(size_t)BATCH * TLEN * HDIM + (size_t)bb * HDIM + gu] = hnew;                 // h_T
            out[(size_t)BATCH * TLEN * HDIM + BATCH * HDIM + (size_t)bb * HDIM + gu] = cnew; // c_T
        }
    }

    // Reset barrier state for the next launch/replay. Safe: a block only
    // increments g_done after its final poll completed, so the last block's
    // reset cannot be observed by any still-polling block.
    __syncthreads();
    if (tid == 0) {
        const unsigned d = atomicAdd(&g_done, 1u);
        if (d == GRID - 1) {
            g_bar = 0;
            g_done = 0;
            __threadfence();
        }
    }
}

// =========================== launch ========================================
extern "C" void kernel_launch(void* const* d_in, const int* in_sizes, int n_in,
                              void* d_out, int out_size) {
    const float* X   = (const float*)d_in[0];   // inputs [32,1024,512]
    const float* Wih = (const float*)d_in[1];   // [4096,512]
    const float* Whh = (const float*)d_in[2];   // [4096,1024]
    const float* bih = (const float*)d_in[3];   // [4096]
    const float* bhh = (const float*)d_in[4];   // [4096]
    float* out = (float*)d_out;                 // outputs | h_T | c_T

    const int dyn_smem = (32 * HDIM + KCH * BATCH) * (int)sizeof(float); // 163840
    cudaFuncSetAttribute(lstm_rec, cudaFuncAttributeMaxDynamicSharedMemorySize, dyn_smem);

    xg_gemm<<<dim3(G4 / BN, (BATCH * TLEN) / BM), 256>>>(X, Wih, bih, bhh);
    lstm_rec<<<GRID, NTH, dyn_smem>>>(Whh, out);
}